// round 3
// baseline (speedup 1.0000x reference)
#include <cuda_runtime.h>
#include <cstdint>

#define HIDDEN 128
#define MAX_NODES 50000
#define MAX_EDGES 500000

// Scratch (static __device__ arrays — no allocation allowed).
__device__ float g_learn1[MAX_NODES * HIDDEN];     // layer-1 output (incl. bias0)
__device__ int   g_counts[MAX_NODES];              // per-row edge counts
__device__ int   g_offsets[MAX_NODES + 1];         // CSR row offsets
__device__ int   g_cursor[MAX_NODES];              // permute cursors
__device__ int2  g_edges[MAX_EDGES];               // row-grouped (col, val-bits)

// ---------------------------------------------------------------------------
// 1) zero per-row counts
// ---------------------------------------------------------------------------
__global__ void zero_counts_kernel(int4* __restrict__ counts, int n4) {
    int i = blockIdx.x * blockDim.x + threadIdx.x;
    if (i < n4) counts[i] = make_int4(0, 0, 0, 0);
}

// ---------------------------------------------------------------------------
// 2) histogram of destination rows — 4 edges/thread (vector load, MLP=4)
// ---------------------------------------------------------------------------
__global__ void hist_kernel(const int* __restrict__ row, int* __restrict__ counts,
                            int n_edges) {
    int base = (blockIdx.x * blockDim.x + threadIdx.x) * 4;
    if (base + 4 <= n_edges) {
        int4 r = __ldg((const int4*)(row + base));
        atomicAdd(&counts[r.x], 1);
        atomicAdd(&counts[r.y], 1);
        atomicAdd(&counts[r.z], 1);
        atomicAdd(&counts[r.w], 1);
    } else {
        for (int e = base; e < n_edges; e++)
            atomicAdd(&counts[__ldg(row + e)], 1);
    }
}

// ---------------------------------------------------------------------------
// 3) single-block exclusive scan of counts -> offsets (+ cursor copy)
// ---------------------------------------------------------------------------
__global__ void scan_kernel(const int* __restrict__ counts,
                            int* __restrict__ offsets,
                            int* __restrict__ cursor, int n) {
    const int T = 1024;
    __shared__ int s[T];
    int t = threadIdx.x;
    int items = (n + T - 1) / T;
    int start = t * items;
    int end = min(start + items, n);

    int sum = 0;
    #pragma unroll 8
    for (int i = start; i < end; i++) sum += __ldg(counts + i);
    s[t] = sum;
    __syncthreads();

    for (int off = 1; off < T; off <<= 1) {
        int v = (t >= off) ? s[t - off] : 0;
        __syncthreads();
        s[t] += v;
        __syncthreads();
    }

    int run = (t > 0) ? s[t - 1] : 0;
    for (int i = start; i < end; i++) {
        offsets[i] = run;
        cursor[i]  = run;
        run += __ldg(counts + i);
    }
    if (t == T - 1) offsets[n] = s[T - 1];
}

// ---------------------------------------------------------------------------
// 4) permute edges into row-grouped order — 4 edges/thread (MLP=4 atomics)
// ---------------------------------------------------------------------------
__global__ void permute_kernel(const int* __restrict__ row,
                               const int* __restrict__ col,
                               const float* __restrict__ val,
                               int* __restrict__ cursor,
                               int2* __restrict__ edges, int n_edges) {
    int base = (blockIdx.x * blockDim.x + threadIdx.x) * 4;
    if (base + 4 <= n_edges) {
        int4   r = __ldg((const int4*)(row + base));
        int4   c = __ldg((const int4*)(col + base));
        float4 v = __ldg((const float4*)(val + base));
        int p0 = atomicAdd(&cursor[r.x], 1);
        int p1 = atomicAdd(&cursor[r.y], 1);
        int p2 = atomicAdd(&cursor[r.z], 1);
        int p3 = atomicAdd(&cursor[r.w], 1);
        edges[p0] = make_int2(c.x, __float_as_int(v.x));
        edges[p1] = make_int2(c.y, __float_as_int(v.y));
        edges[p2] = make_int2(c.z, __float_as_int(v.z));
        edges[p3] = make_int2(c.w, __float_as_int(v.w));
    } else {
        for (int e = base; e < n_edges; e++) {
            int p = atomicAdd(&cursor[__ldg(row + e)], 1);
            edges[p] = make_int2(__ldg(col + e), __float_as_int(__ldg(val + e)));
        }
    }
}

// ---------------------------------------------------------------------------
// 5) CSR SpMM, one warp per destination row, chunk-of-4 pipelined gathers.
//    FUSE_FINAL=0:  y[r] = sum(val * x[col]) + bias_row
//    FUSE_FINAL=1:  y[r] = (fea[r] + x[r] + sum + bias_row) / 3   (x == learn1)
// ---------------------------------------------------------------------------
template <int FUSE_FINAL>
__global__ void spmm_csr_kernel(const float4* __restrict__ x,
                                float4* __restrict__ y,
                                const int* __restrict__ offsets,
                                const int2* __restrict__ edges,
                                const float4* __restrict__ bias4,  // 32 float4
                                const float4* __restrict__ fea,    // residual
                                int n_nodes) {
    int gtid = blockIdx.x * blockDim.x + threadIdx.x;
    int r = gtid >> 5;
    if (r >= n_nodes) return;
    int lane = threadIdx.x & 31;

    float4 acc = __ldg(bias4 + lane);

    int beg = __ldg(offsets + r);
    int end = __ldg(offsets + r + 1);

    for (int i = beg; i < end; i += 4) {
        int m = end - i;
        // phase 1: edge descriptors (uniform broadcast loads)
        int2 e0, e1, e2, e3;
        e0 = __ldg(edges + i);
        if (m > 1) e1 = __ldg(edges + i + 1);
        if (m > 2) e2 = __ldg(edges + i + 2);
        if (m > 3) e3 = __ldg(edges + i + 3);
        // phase 2: issue all row gathers before any FMA (MLP = 4)
        float4 x0, x1, x2, x3;
        x0 = __ldg(x + (size_t)e0.x * 32 + lane);
        if (m > 1) x1 = __ldg(x + (size_t)e1.x * 32 + lane);
        if (m > 2) x2 = __ldg(x + (size_t)e2.x * 32 + lane);
        if (m > 3) x3 = __ldg(x + (size_t)e3.x * 32 + lane);
        // phase 3: accumulate
        float v0 = __int_as_float(e0.y);
        acc.x += v0 * x0.x; acc.y += v0 * x0.y; acc.z += v0 * x0.z; acc.w += v0 * x0.w;
        if (m > 1) {
            float v1 = __int_as_float(e1.y);
            acc.x += v1 * x1.x; acc.y += v1 * x1.y; acc.z += v1 * x1.z; acc.w += v1 * x1.w;
        }
        if (m > 2) {
            float v2 = __int_as_float(e2.y);
            acc.x += v2 * x2.x; acc.y += v2 * x2.y; acc.z += v2 * x2.z; acc.w += v2 * x2.w;
        }
        if (m > 3) {
            float v3 = __int_as_float(e3.y);
            acc.x += v3 * x3.x; acc.y += v3 * x3.y; acc.z += v3 * x3.z; acc.w += v3 * x3.w;
        }
    }

    size_t idx = (size_t)r * 32 + lane;
    if (FUSE_FINAL) {
        const float inv3 = 1.0f / 3.0f;
        float4 f  = __ldg(fea + idx);
        float4 l1 = __ldg(x + idx);      // x == learn1 here
        acc.x = (f.x + l1.x + acc.x) * inv3;
        acc.y = (f.y + l1.y + acc.y) * inv3;
        acc.z = (f.z + l1.z + acc.z) * inv3;
        acc.w = (f.w + l1.w + acc.w) * inv3;
    }
    y[idx] = acc;
}

extern "C" void kernel_launch(void* const* d_in, const int* in_sizes, int n_in,
                              void* d_out, int out_size) {
    const float* fea     = (const float*)d_in[0];   // [N, 128]
    const int*   adj_row = (const int*)  d_in[1];   // [E]
    const int*   adj_col = (const int*)  d_in[2];   // [E]
    const float* adj_val = (const float*)d_in[3];   // [E]
    const float* bias    = (const float*)d_in[4];   // [2, 128]

    int n_edges = in_sizes[1];
    int n_nodes = in_sizes[0] / HIDDEN;

    float* learn1; cudaGetSymbolAddress((void**)&learn1, g_learn1);
    int*   counts; cudaGetSymbolAddress((void**)&counts, g_counts);
    int*   offs;   cudaGetSymbolAddress((void**)&offs,   g_offsets);
    int*   cursor; cudaGetSymbolAddress((void**)&cursor, g_cursor);
    int2*  edges;  cudaGetSymbolAddress((void**)&edges,  g_edges);
    float* out = (float*)d_out;

    const int TPB = 256;

    // 1) zero counts (vectorized; MAX_NODES may not be /4 — round up via scalar pad)
    {
        int n4 = (n_nodes + 3) / 4;   // g_counts is sized MAX_NODES; 50000 % 4 == 0
        zero_counts_kernel<<<(n4 + TPB - 1) / TPB, TPB>>>((int4*)counts, n4);
    }

    // 2) histogram rows, 4 edges/thread
    {
        int threads = (n_edges + 3) / 4;
        hist_kernel<<<(threads + TPB - 1) / TPB, TPB>>>(adj_row, counts, n_edges);
    }

    // 3) scan -> offsets (+cursor)
    scan_kernel<<<1, 1024>>>(counts, offs, cursor, n_nodes);

    // 4) permute edges into row-grouped order, 4 edges/thread
    {
        int threads = (n_edges + 3) / 4;
        permute_kernel<<<(threads + TPB - 1) / TPB, TPB>>>(adj_row, adj_col, adj_val,
                                                           cursor, edges, n_edges);
    }

    // 5) layer 1: learn1 = spmm(fea) + bias0   (warp per row, no atomics)
    {
        int blocks = (n_nodes * 32 + TPB - 1) / TPB;
        spmm_csr_kernel<0><<<blocks, TPB>>>((const float4*)fea, (float4*)learn1,
                                            offs, edges, (const float4*)bias,
                                            nullptr, n_nodes);
    }

    // 6) layer 2 + fused final: out = (fea + learn1 + spmm(learn1) + bias1)/3
    {
        int blocks = (n_nodes * 32 + TPB - 1) / TPB;
        spmm_csr_kernel<1><<<blocks, TPB>>>((const float4*)learn1, (float4*)out,
                                            offs, edges,
                                            (const float4*)(bias + HIDDEN),
                                            (const float4*)fea, n_nodes);
    }
}

// round 4
// speedup vs baseline: 1.8279x; 1.8279x over previous
#include <cuda_runtime.h>
#include <cstdint>

#define HIDDEN 128
#define MAX_NODES 50000
#define MAX_EDGES 500000
#define SCAN_CHUNK 1024
#define MAX_SBLOCKS ((MAX_NODES + SCAN_CHUNK - 1) / SCAN_CHUNK)   // 49

// Scratch (static __device__ arrays — no allocation allowed).
__device__ float g_learn1[MAX_NODES * HIDDEN];   // layer-1 output (incl. bias0)
__device__ int   g_counts[MAX_NODES];            // per-row edge counts
__device__ int   g_offsets[MAX_NODES + 1];       // CSR row offsets
__device__ int   g_rank[MAX_EDGES];              // within-row rank per edge
__device__ int   g_bsum[MAX_SBLOCKS];            // scan block sums
__device__ int2  g_edges[MAX_EDGES];             // row-grouped (col, val-bits)

// ---------------------------------------------------------------------------
// 1) zero counts; also pre-write offsets[n] = E (total).
// ---------------------------------------------------------------------------
__global__ void zero_kernel(int* __restrict__ counts, int n,
                            int* __restrict__ offsets, int n_edges) {
    int i = blockIdx.x * blockDim.x + threadIdx.x;
    if (i < n) counts[i] = 0;
    if (i == 0) offsets[n] = n_edges;
}

// ---------------------------------------------------------------------------
// 2) fused histogram + rank: rank[e] = old count of row[e]
// ---------------------------------------------------------------------------
__global__ void hist_rank_kernel(const int* __restrict__ row,
                                 int* __restrict__ counts,
                                 int* __restrict__ rank, int n_edges) {
    int e = blockIdx.x * blockDim.x + threadIdx.x;
    if (e < n_edges) rank[e] = atomicAdd(&counts[__ldg(row + e)], 1);
}

// ---------------------------------------------------------------------------
// 3a) per-1024-chunk block sums (49 blocks, 256 threads, 4 counts/thread)
// ---------------------------------------------------------------------------
__global__ void scan_bsum_kernel(const int* __restrict__ counts,
                                 int* __restrict__ bsum, int n) {
    __shared__ int s[256];
    int t = threadIdx.x;
    int base = blockIdx.x * SCAN_CHUNK + t * 4;
    int sum = 0;
    #pragma unroll
    for (int k = 0; k < 4; k++)
        sum += (base + k < n) ? __ldg(counts + base + k) : 0;
    s[t] = sum;
    __syncthreads();
    for (int off = 1; off < 256; off <<= 1) {
        int v = (t >= off) ? s[t - off] : 0;
        __syncthreads();
        s[t] += v;
        __syncthreads();
    }
    if (t == 255) bsum[blockIdx.x] = s[255];
}

// ---------------------------------------------------------------------------
// 3b) final scan: each block redundantly scans the 49 block sums in smem,
//     then block-scans its own 1024 counts and writes exclusive offsets.
// ---------------------------------------------------------------------------
__global__ void scan_offsets_kernel(const int* __restrict__ counts,
                                    const int* __restrict__ bsum,
                                    int* __restrict__ offsets,
                                    int n, int nblocks) {
    __shared__ int s[256];
    __shared__ int bpref;
    int t = threadIdx.x;
    int b = blockIdx.x;

    // exclusive prefix of block sums up to b (redundant per block; 49 ints)
    if (t == 0) {
        int p = 0;
        for (int i = 0; i < b; i++) p += bsum[i];
        bpref = p;
    }

    int base = b * SCAN_CHUNK + t * 4;
    int c0 = (base + 0 < n) ? __ldg(counts + base + 0) : 0;
    int c1 = (base + 1 < n) ? __ldg(counts + base + 1) : 0;
    int c2 = (base + 2 < n) ? __ldg(counts + base + 2) : 0;
    int c3 = (base + 3 < n) ? __ldg(counts + base + 3) : 0;
    s[t] = c0 + c1 + c2 + c3;
    __syncthreads();
    for (int off = 1; off < 256; off <<= 1) {
        int v = (t >= off) ? s[t - off] : 0;
        __syncthreads();
        s[t] += v;
        __syncthreads();
    }

    int run = bpref + ((t > 0) ? s[t - 1] : 0);
    if (base + 0 < n) offsets[base + 0] = run; run += c0;
    if (base + 1 < n) offsets[base + 1] = run; run += c1;
    if (base + 2 < n) offsets[base + 2] = run; run += c2;
    if (base + 3 < n) offsets[base + 3] = run;
}

// ---------------------------------------------------------------------------
// 4) permute edges — NO atomics: pos = offsets[row] + rank
// ---------------------------------------------------------------------------
__global__ void permute_kernel(const int* __restrict__ row,
                               const int* __restrict__ col,
                               const float* __restrict__ val,
                               const int* __restrict__ rank,
                               const int* __restrict__ offsets,
                               int2* __restrict__ edges, int n_edges) {
    int e = blockIdx.x * blockDim.x + threadIdx.x;
    if (e >= n_edges) return;
    int r = __ldg(row + e);
    int pos = __ldg(offsets + r) + __ldg(rank + e);
    edges[pos] = make_int2(__ldg(col + e), __float_as_int(__ldg(val + e)));
}

// ---------------------------------------------------------------------------
// 5) CSR SpMM, warp per row. Main loop: chunk-8 (MLP=8 gathers).
//    Tail: predicated chunk covering up to 7 edges, loads issued before FMAs.
//    FUSE_FINAL=0:  y[r] = sum(val * x[col]) + bias_row
//    FUSE_FINAL=1:  y[r] = (fea[r] + x[r] + sum + bias_row) / 3   (x==learn1)
// ---------------------------------------------------------------------------
template <int FUSE_FINAL>
__global__ void __launch_bounds__(256)
spmm_csr_kernel(const float4* __restrict__ x,
                float4* __restrict__ y,
                const int* __restrict__ offsets,
                const int2* __restrict__ edges,
                const float4* __restrict__ bias4,   // 32 float4
                const float4* __restrict__ fea,     // residual (layer 2)
                int n_nodes) {
    int gtid = blockIdx.x * blockDim.x + threadIdx.x;
    int r = gtid >> 5;
    if (r >= n_nodes) return;
    int lane = threadIdx.x & 31;

    float4 acc = __ldg(bias4 + lane);

    int beg = __ldg(offsets + r);
    int end = __ldg(offsets + r + 1);

    int i = beg;
    // full chunks of 8: all edge loads, then all gathers, then FMAs
    for (; i + 8 <= end; i += 8) {
        int2 e[8];
        float4 xv[8];
        #pragma unroll
        for (int k = 0; k < 8; k++) e[k] = __ldg(edges + i + k);
        #pragma unroll
        for (int k = 0; k < 8; k++)
            xv[k] = __ldg(x + (size_t)e[k].x * 32 + lane);
        #pragma unroll
        for (int k = 0; k < 8; k++) {
            float v = __int_as_float(e[k].y);
            acc.x += v * xv[k].x; acc.y += v * xv[k].y;
            acc.z += v * xv[k].z; acc.w += v * xv[k].w;
        }
    }
    // predicated tail (0..7 edges), loads still batched before FMAs
    int m = end - i;
    if (m > 0) {
        int2 e[7];
        float4 xv[7];
        #pragma unroll
        for (int k = 0; k < 7; k++)
            if (k < m) e[k] = __ldg(edges + i + k);
        #pragma unroll
        for (int k = 0; k < 7; k++)
            if (k < m) xv[k] = __ldg(x + (size_t)e[k].x * 32 + lane);
        #pragma unroll
        for (int k = 0; k < 7; k++)
            if (k < m) {
                float v = __int_as_float(e[k].y);
                acc.x += v * xv[k].x; acc.y += v * xv[k].y;
                acc.z += v * xv[k].z; acc.w += v * xv[k].w;
            }
    }

    size_t idx = (size_t)r * 32 + lane;
    if (FUSE_FINAL) {
        const float inv3 = 1.0f / 3.0f;
        float4 f  = __ldg(fea + idx);
        float4 l1 = __ldg(x + idx);     // x == learn1 here
        acc.x = (f.x + l1.x + acc.x) * inv3;
        acc.y = (f.y + l1.y + acc.y) * inv3;
        acc.z = (f.z + l1.z + acc.z) * inv3;
        acc.w = (f.w + l1.w + acc.w) * inv3;
    }
    y[idx] = acc;
}

extern "C" void kernel_launch(void* const* d_in, const int* in_sizes, int n_in,
                              void* d_out, int out_size) {
    const float* fea     = (const float*)d_in[0];   // [N, 128]
    const int*   adj_row = (const int*)  d_in[1];   // [E]
    const int*   adj_col = (const int*)  d_in[2];   // [E]
    const float* adj_val = (const float*)d_in[3];   // [E]
    const float* bias    = (const float*)d_in[4];   // [2, 128]

    int n_edges = in_sizes[1];
    int n_nodes = in_sizes[0] / HIDDEN;
    int nblocks_scan = (n_nodes + SCAN_CHUNK - 1) / SCAN_CHUNK;

    float* learn1; cudaGetSymbolAddress((void**)&learn1, g_learn1);
    int*   counts; cudaGetSymbolAddress((void**)&counts, g_counts);
    int*   offs;   cudaGetSymbolAddress((void**)&offs,   g_offsets);
    int*   rank;   cudaGetSymbolAddress((void**)&rank,   g_rank);
    int*   bsum;   cudaGetSymbolAddress((void**)&bsum,   g_bsum);
    int2*  edges;  cudaGetSymbolAddress((void**)&edges,  g_edges);
    float* out = (float*)d_out;

    const int TPB = 256;

    // 1) zero counts (+ offsets[n] = E)
    zero_kernel<<<(n_nodes + TPB - 1) / TPB, TPB>>>(counts, n_nodes, offs, n_edges);

    // 2) fused histogram + rank
    hist_rank_kernel<<<(n_edges + TPB - 1) / TPB, TPB>>>(adj_row, counts, rank, n_edges);

    // 3) two-pass parallel scan -> offsets
    scan_bsum_kernel<<<nblocks_scan, 256>>>(counts, bsum, n_nodes);
    scan_offsets_kernel<<<nblocks_scan, 256>>>(counts, bsum, offs, n_nodes, nblocks_scan);

    // 4) permute edges (no atomics)
    permute_kernel<<<(n_edges + TPB - 1) / TPB, TPB>>>(adj_row, adj_col, adj_val,
                                                       rank, offs, edges, n_edges);

    // 5) layer 1: learn1 = spmm(fea) + bias0   (launch #6 — ncu target)
    {
        int blocks = (n_nodes * 32 + TPB - 1) / TPB;
        spmm_csr_kernel<0><<<blocks, TPB>>>((const float4*)fea, (float4*)learn1,
                                            offs, edges, (const float4*)bias,
                                            nullptr, n_nodes);
    }

    // 6) layer 2 + fused final: out = (fea + learn1 + spmm(learn1) + bias1)/3
    {
        int blocks = (n_nodes * 32 + TPB - 1) / TPB;
        spmm_csr_kernel<1><<<blocks, TPB>>>((const float4*)learn1, (float4*)out,
                                            offs, edges,
                                            (const float4*)(bias + HIDDEN),
                                            (const float4*)fea, n_nodes);
    }
}

// round 5
// speedup vs baseline: 1.8732x; 1.0247x over previous
#include <cuda_runtime.h>
#include <cuda_fp16.h>
#include <cstdint>

#define HIDDEN 128
#define MAX_NODES 50000
#define MAX_EDGES 500000
#define SCAN_CHUNK 1024
#define MAX_SBLOCKS ((MAX_NODES + SCAN_CHUNK - 1) / SCAN_CHUNK)   // 49

// Scratch (static __device__ arrays — no allocation allowed).
__device__ float g_learn1[MAX_NODES * HIDDEN];     // layer-1 output fp32
__device__ uint2 g_feah[MAX_NODES * 32];           // fea as fp16 (4 halfs/uint2)
__device__ uint2 g_learn1h[MAX_NODES * 32];        // learn1 as fp16
__device__ int   g_counts[MAX_NODES];
__device__ int   g_offsets[MAX_NODES + 1];
__device__ int   g_rank[MAX_EDGES];
__device__ int   g_bsum[MAX_SBLOCKS];
__device__ int2  g_edges[MAX_EDGES];               // row-grouped (col, val-bits)

// fp16x4 unpack + FMA into fp32 accumulator
__device__ __forceinline__ void fma4h(float4& acc, float v, uint2 g) {
    __half2 h01 = *reinterpret_cast<__half2*>(&g.x);
    __half2 h23 = *reinterpret_cast<__half2*>(&g.y);
    float2 f01 = __half22float2(h01);
    float2 f23 = __half22float2(h23);
    acc.x += v * f01.x; acc.y += v * f01.y;
    acc.z += v * f23.x; acc.w += v * f23.y;
}

__device__ __forceinline__ uint2 pack4h(float4 a) {
    __half2 h01 = __floats2half2_rn(a.x, a.y);
    __half2 h23 = __floats2half2_rn(a.z, a.w);
    uint2 g;
    g.x = *reinterpret_cast<uint32_t*>(&h01);
    g.y = *reinterpret_cast<uint32_t*>(&h23);
    return g;
}

// ---------------------------------------------------------------------------
// 1) prep: convert fea -> fp16 shadow, zero counts
// ---------------------------------------------------------------------------
__global__ void prep_kernel(const float4* __restrict__ fea,
                            uint2* __restrict__ feah,
                            int* __restrict__ counts,
                            int n_nodes, int total4) {
    int i = blockIdx.x * blockDim.x + threadIdx.x;
    if (i < total4) feah[i] = pack4h(__ldg(fea + i));
    if (i < n_nodes) counts[i] = 0;
}

// ---------------------------------------------------------------------------
// 2) fused histogram + rank
// ---------------------------------------------------------------------------
__global__ void hist_rank_kernel(const int* __restrict__ row,
                                 int* __restrict__ counts,
                                 int* __restrict__ rank, int n_edges) {
    int e = blockIdx.x * blockDim.x + threadIdx.x;
    if (e < n_edges) rank[e] = atomicAdd(&counts[__ldg(row + e)], 1);
}

// ---------------------------------------------------------------------------
// 3a) per-1024-chunk block sums
// ---------------------------------------------------------------------------
__global__ void scan_bsum_kernel(const int* __restrict__ counts,
                                 int* __restrict__ bsum, int n) {
    __shared__ int s[256];
    int t = threadIdx.x;
    int base = blockIdx.x * SCAN_CHUNK + t * 4;
    int sum = 0;
    #pragma unroll
    for (int k = 0; k < 4; k++)
        sum += (base + k < n) ? __ldg(counts + base + k) : 0;
    s[t] = sum;
    __syncthreads();
    for (int off = 1; off < 256; off <<= 1) {
        int v = (t >= off) ? s[t - off] : 0;
        __syncthreads();
        s[t] += v;
        __syncthreads();
    }
    if (t == 255) bsum[blockIdx.x] = s[255];
}

// ---------------------------------------------------------------------------
// 3b) final scan — bsum prefix computed by a PARALLEL smem scan (64 threads),
//     then block-local scan of 1024 counts -> exclusive offsets.
// ---------------------------------------------------------------------------
__global__ void scan_offsets_kernel(const int* __restrict__ counts,
                                    const int* __restrict__ bsum,
                                    int* __restrict__ offsets,
                                    int n, int nblocks) {
    __shared__ int s[256];
    __shared__ int sb[64];
    int t = threadIdx.x;
    int b = blockIdx.x;

    if (t < 64) sb[t] = (t < nblocks) ? __ldg(bsum + t) : 0;
    __syncthreads();
    for (int off = 1; off < 64; off <<= 1) {
        int v = (t >= off && t < 64) ? sb[t - off] : 0;
        __syncthreads();
        if (t < 64) sb[t] += v;
        __syncthreads();
    }
    int bpref = (b > 0) ? sb[b - 1] : 0;   // exclusive prefix of this block

    int base = b * SCAN_CHUNK + t * 4;
    int c0 = (base + 0 < n) ? __ldg(counts + base + 0) : 0;
    int c1 = (base + 1 < n) ? __ldg(counts + base + 1) : 0;
    int c2 = (base + 2 < n) ? __ldg(counts + base + 2) : 0;
    int c3 = (base + 3 < n) ? __ldg(counts + base + 3) : 0;
    s[t] = c0 + c1 + c2 + c3;
    __syncthreads();
    for (int off = 1; off < 256; off <<= 1) {
        int v = (t >= off) ? s[t - off] : 0;
        __syncthreads();
        s[t] += v;
        __syncthreads();
    }

    int run = bpref + ((t > 0) ? s[t - 1] : 0);
    if (base + 0 < n) offsets[base + 0] = run; run += c0;
    if (base + 1 < n) offsets[base + 1] = run; run += c1;
    if (base + 2 < n) offsets[base + 2] = run; run += c2;
    if (base + 3 < n) offsets[base + 3] = run;

    if (b == 0 && t == 0) offsets[n] = sb[nblocks - 1];  // total edges
}

// ---------------------------------------------------------------------------
// 4) permute edges — no atomics: pos = offsets[row] + rank
// ---------------------------------------------------------------------------
__global__ void permute_kernel(const int* __restrict__ row,
                               const int* __restrict__ col,
                               const float* __restrict__ val,
                               const int* __restrict__ rank,
                               const int* __restrict__ offsets,
                               int2* __restrict__ edges, int n_edges) {
    int e = blockIdx.x * blockDim.x + threadIdx.x;
    if (e >= n_edges) return;
    int r = __ldg(row + e);
    int pos = __ldg(offsets + r) + __ldg(rank + e);
    edges[pos] = make_int2(__ldg(col + e), __float_as_int(__ldg(val + e)));
}

// ---------------------------------------------------------------------------
// 5) layer 1: learn1 = spmm_h(fea_h) + bias0 ; also emit learn1 as fp16
//    warp per row; fp16 gathers (8B/lane), fp32 accumulate; chunk-8 MLP.
// ---------------------------------------------------------------------------
__global__ void __launch_bounds__(256)
spmm1_kernel(const uint2* __restrict__ xh,
             float4* __restrict__ y,
             uint2* __restrict__ yh,
             const int* __restrict__ offsets,
             const int2* __restrict__ edges,
             const float4* __restrict__ bias4,   // 32 float4
             int n_nodes) {
    int gtid = blockIdx.x * blockDim.x + threadIdx.x;
    int r = gtid >> 5;
    if (r >= n_nodes) return;
    int lane = threadIdx.x & 31;

    float4 acc = __ldg(bias4 + lane);
    int beg = __ldg(offsets + r);
    int end = __ldg(offsets + r + 1);

    int i = beg;
    for (; i + 8 <= end; i += 8) {
        int2 e[8]; uint2 g[8];
        #pragma unroll
        for (int k = 0; k < 8; k++) e[k] = __ldg(edges + i + k);
        #pragma unroll
        for (int k = 0; k < 8; k++)
            g[k] = __ldg(xh + (size_t)e[k].x * 32 + lane);
        #pragma unroll
        for (int k = 0; k < 8; k++)
            fma4h(acc, __int_as_float(e[k].y), g[k]);
    }
    int m = end - i;
    if (m > 0) {
        int2 e[7]; uint2 g[7];
        #pragma unroll
        for (int k = 0; k < 7; k++) if (k < m) e[k] = __ldg(edges + i + k);
        #pragma unroll
        for (int k = 0; k < 7; k++)
            if (k < m) g[k] = __ldg(xh + (size_t)e[k].x * 32 + lane);
        #pragma unroll
        for (int k = 0; k < 7; k++)
            if (k < m) fma4h(acc, __int_as_float(e[k].y), g[k]);
    }

    size_t idx = (size_t)r * 32 + lane;
    y[idx]  = acc;
    yh[idx] = pack4h(acc);
}

// ---------------------------------------------------------------------------
// 6) layer 2 + fused final: out = (fea + learn1 + spmm_h(learn1_h)+bias1)/3
// ---------------------------------------------------------------------------
__global__ void __launch_bounds__(256)
spmm2_kernel(const uint2* __restrict__ xh,       // learn1 fp16
             const float4* __restrict__ learn1,  // learn1 fp32
             const float4* __restrict__ fea,
             float4* __restrict__ out,
             const int* __restrict__ offsets,
             const int2* __restrict__ edges,
             const float4* __restrict__ bias4,
             int n_nodes) {
    int gtid = blockIdx.x * blockDim.x + threadIdx.x;
    int r = gtid >> 5;
    if (r >= n_nodes) return;
    int lane = threadIdx.x & 31;

    float4 acc = __ldg(bias4 + lane);
    int beg = __ldg(offsets + r);
    int end = __ldg(offsets + r + 1);

    int i = beg;
    for (; i + 8 <= end; i += 8) {
        int2 e[8]; uint2 g[8];
        #pragma unroll
        for (int k = 0; k < 8; k++) e[k] = __ldg(edges + i + k);
        #pragma unroll
        for (int k = 0; k < 8; k++)
            g[k] = __ldg(xh + (size_t)e[k].x * 32 + lane);
        #pragma unroll
        for (int k = 0; k < 8; k++)
            fma4h(acc, __int_as_float(e[k].y), g[k]);
    }
    int m = end - i;
    if (m > 0) {
        int2 e[7]; uint2 g[7];
        #pragma unroll
        for (int k = 0; k < 7; k++) if (k < m) e[k] = __ldg(edges + i + k);
        #pragma unroll
        for (int k = 0; k < 7; k++)
            if (k < m) g[k] = __ldg(xh + (size_t)e[k].x * 32 + lane);
        #pragma unroll
        for (int k = 0; k < 7; k++)
            if (k < m) fma4h(acc, __int_as_float(e[k].y), g[k]);
    }

    size_t idx = (size_t)r * 32 + lane;
    const float inv3 = 1.0f / 3.0f;
    float4 f  = __ldg(fea + idx);
    float4 l1 = __ldg(learn1 + idx);
    acc.x = (f.x + l1.x + acc.x) * inv3;
    acc.y = (f.y + l1.y + acc.y) * inv3;
    acc.z = (f.z + l1.z + acc.z) * inv3;
    acc.w = (f.w + l1.w + acc.w) * inv3;
    out[idx] = acc;
}

extern "C" void kernel_launch(void* const* d_in, const int* in_sizes, int n_in,
                              void* d_out, int out_size) {
    const float* fea     = (const float*)d_in[0];
    const int*   adj_row = (const int*)  d_in[1];
    const int*   adj_col = (const int*)  d_in[2];
    const float* adj_val = (const float*)d_in[3];
    const float* bias    = (const float*)d_in[4];

    int n_edges = in_sizes[1];
    int n_nodes = in_sizes[0] / HIDDEN;
    int total4  = n_nodes * 32;
    int nblocks_scan = (n_nodes + SCAN_CHUNK - 1) / SCAN_CHUNK;

    float* learn1;  cudaGetSymbolAddress((void**)&learn1,  g_learn1);
    uint2* feah;    cudaGetSymbolAddress((void**)&feah,    g_feah);
    uint2* learn1h; cudaGetSymbolAddress((void**)&learn1h, g_learn1h);
    int*   counts;  cudaGetSymbolAddress((void**)&counts,  g_counts);
    int*   offs;    cudaGetSymbolAddress((void**)&offs,    g_offsets);
    int*   rank;    cudaGetSymbolAddress((void**)&rank,    g_rank);
    int*   bsum;    cudaGetSymbolAddress((void**)&bsum,    g_bsum);
    int2*  edges;   cudaGetSymbolAddress((void**)&edges,   g_edges);
    float* out = (float*)d_out;

    const int TPB = 256;

    // 1) convert fea -> fp16, zero counts
    prep_kernel<<<(total4 + TPB - 1) / TPB, TPB>>>((const float4*)fea, feah,
                                                   counts, n_nodes, total4);

    // 2) histogram + rank
    hist_rank_kernel<<<(n_edges + TPB - 1) / TPB, TPB>>>(adj_row, counts, rank, n_edges);

    // 3) parallel two-pass scan -> offsets
    scan_bsum_kernel<<<nblocks_scan, 256>>>(counts, bsum, n_nodes);
    scan_offsets_kernel<<<nblocks_scan, 256>>>(counts, bsum, offs, n_nodes, nblocks_scan);

    // 4) permute edges (no atomics)
    permute_kernel<<<(n_edges + TPB - 1) / TPB, TPB>>>(adj_row, adj_col, adj_val,
                                                       rank, offs, edges, n_edges);

    // 5) layer 1
    {
        int blocks = (n_nodes * 32 + TPB - 1) / TPB;
        spmm1_kernel<<<blocks, TPB>>>(feah, (float4*)learn1, learn1h,
                                      offs, edges, (const float4*)bias, n_nodes);
    }

    // 6) layer 2 + fused final
    {
        int blocks = (n_nodes * 32 + TPB - 1) / TPB;
        spmm2_kernel<<<blocks, TPB>>>(learn1h, (const float4*)learn1,
                                      (const float4*)fea, (float4*)out,
                                      offs, edges,
                                      (const float4*)(bias + HIDDEN), n_nodes);
    }
}